// round 13
// baseline (speedup 1.0000x reference)
#include <cuda_runtime.h>
#include <math.h>
#include <stdint.h>

// ---------------------------------------------------------------------------
// RDHAgent forward. R13: R12 + software-pipelined GEMM loop (register
// prefetch of next k-block's A(LDS) and B(LDG) fragments; peeled head/tail,
// no conditionals in the steady-state body). Addressing identical to R12.
// ---------------------------------------------------------------------------

#define NBA   384
#define KNET  650
#define KPAD  672
#define NKB   (KPAD/8)
#define GPITCH 676

__device__ float g_Mred[3 * KPAD * 64];   // tf32-pre-rounded

__device__ __forceinline__ uint32_t cvt_tf32(float x){
    uint32_t r; asm("cvt.rna.tf32.f32 %0, %1;" : "=r"(r) : "f"(x)); return r;
}
__device__ __forceinline__ float tf32f(float x){
    return __uint_as_float(cvt_tf32(x));
}
__device__ __forceinline__ void mma_tf32(float* d, const uint32_t* a, uint32_t b0, uint32_t b1){
    asm("mma.sync.aligned.m16n8k8.row.col.f32.tf32.tf32.f32 "
        "{%0,%1,%2,%3},{%4,%5,%6,%7},{%8,%9},{%0,%1,%2,%3};"
        : "+f"(d[0]),"+f"(d[1]),"+f"(d[2]),"+f"(d[3])
        : "r"(a[0]),"r"(a[1]),"r"(a[2]),"r"(a[3]), "r"(b0),"r"(b1));
}

// ---------------- K0: build Mred[net][K][dh] (tf32-rounded) ----------------
__global__ void k_mred(const float* __restrict__ wA2, const float* __restrict__ bA2,
                       const float* __restrict__ wE2, const float* __restrict__ bE2,
                       const float* __restrict__ wL2, const float* __restrict__ bL2,
                       const float* __restrict__ mergw) {
    int K = blockIdx.x, net = blockIdx.y, dh = threadIdx.x;
    float outv = 0.f;
    if (K < KNET) {
        float m0 = mergw[dh], m1 = mergw[64+dh], m2 = mergw[128+dh], m3 = mergw[192+dh];
        float mx = fmaxf(fmaxf(m0,m1), fmaxf(m2,m3));
        float e0 = expf(m0-mx), e1 = expf(m1-mx), e2 = expf(m2-mx), e3 = expf(m3-mx);
        float inv = 1.f/(e0+e1+e2+e3);
        int j10 = K/10;
        int k   = K - j10*10;
        const float* w2 = (net==0)?wA2:((net==1)?wE2:wL2);
        const float* b2 = (net==0)?bA2:((net==1)?bE2:bL2);
        const float* src = (j10 < 64) ? (w2 + j10*2560) : b2;
        int base = k*256 + dh;
        outv = (e0*src[base] + e1*src[base+64] + e2*src[base+128] + e3*src[base+192]) * inv;
    }
    g_Mred[(net*KPAD + K)*64 + dh] = tf32f(outv);
}

// ---------------- K1: fused ----------------
__global__ void __launch_bounds__(384, 1) k_fused(
    const float* __restrict__ obs, const float* __restrict__ acts,
    const float* __restrict__ wA1, const float* __restrict__ bA1,
    const float* __restrict__ wE1, const float* __restrict__ bE1,
    const float* __restrict__ wL1, const float* __restrict__ bL1,
    const float* __restrict__ fc1w, const float* __restrict__ fc1b,
    const float* __restrict__ fc2w, const float* __restrict__ fc2b,
    float* __restrict__ out)
{
    extern __shared__ float sm[];
    float* Gs    = sm;
    float* sW1   = sm + 48672;
    float* sB1   = sm + 50400;
    float* sFeat = sm + 50592;
    float* sS    = sm + 52512;
    float* sF    = sm + 52764;   // fc1w [67][64]
    float* s_velx = sS;        // [24]
    float* s_vely = sS + 24;
    float* s_sint = sS + 48;
    float* s_cost = sS + 72;
    float* s_sina = sS + 96;
    float* s_cosa = sS + 120;
    float* s_rbf  = sS + 144;  // [24][3]
    float* s_act  = sS + 216;  // [3][3]
    float* s_q    = sS + 228;  // [24]

    const int t   = threadIdx.x;
    const int g   = t >> 7;            // build-phase net group 0..2
    const int tg  = t & 127;
    const int ba0 = blockIdx.x * 3;

    // ---- stage fc1w early ----
    {
        const float4* f4 = (const float4*)fc1w;
        float4* d4 = (float4*)sF;
        for (int idx = t; idx < 67*16; idx += 384) d4[idx] = f4[idx];
    }

    // ---- stage W1/b1 ----
    for (int idx = t; idx < 576; idx += 384) {
        sW1[idx] = wA1[idx]; sW1[576+idx] = wE1[idx]; sW1[1152+idx] = wL1[idx];
    }
    if (t < 192) {
        int n = t >> 6, c = t & 63;
        sB1[n*64+c] = (n==0)?bA1[c]:((n==1)?bE1[c]:bL1[c]);
    }

    // ---- per-entity scalars ----
    if (t < 24) {
        int bl = t >> 3, j = t & 7;
        const float* ob = obs + (ba0 + bl)*30;
        float px,py,vx,vy;
        if (j < 2)      { px=ob[10+2*j];     py=ob[11+2*j];     vx=ob[20+2*j];     vy=ob[21+2*j]; }
        else if (j < 5) { px=ob[14+2*(j-2)]; py=ob[15+2*(j-2)]; vx=ob[24+2*(j-2)]; vy=ob[25+2*(j-2)]; }
        else            { px=ob[4+2*(j-5)];  py=ob[5+2*(j-5)];  vx=-ob[0];         vy=-ob[1]; }
        float dist = sqrtf(px*px+py*py);
        float id = 1.f/(dist+1e-7f);
        s_sint[t]=py*id; s_cost[t]=px*id;
        float vn = sqrtf(vx*vx+vy*vy);
        float iv = 1.f/(vn+1e-7f);
        s_sina[t]=vy*iv; s_cosa[t]=vx*iv;
        s_velx[t]=vx; s_vely[t]=vy;
        s_rbf[t*3+0]=expf(-0.02f*dist*dist);
        float d1=dist-5.f;  s_rbf[t*3+1]=expf(-0.02f*d1*d1);
        float d2=dist-10.f; s_rbf[t*3+2]=expf(-0.02f*d2*d2);
    } else if (t < 27) {
        int bl = t - 24;
        float ax = acts[(ba0+bl)*2], ay = acts[(ba0+bl)*2+1];
        float an = sqrtf(ax*ax+ay*ay);
        s_act[bl*3+0]=an; s_act[bl*3+1]=ay/(an+1e-7f); s_act[bl*3+2]=ax/(an+1e-7f);
    }
    __syncthreads();

    // ---- feat'[10] per (bl,i,j) ----
    if (t < 192) {
        int bl = t >> 6, i = (t >> 3) & 7, j = t & 7;
        int oI = bl*8 + i, oJ = bl*8 + j;
        float* fd = sFeat + t*10;
        fd[0] = s_rbf[oJ*3+0];
        fd[1] = s_rbf[oJ*3+1];
        fd[2] = s_rbf[oJ*3+2];
        float si=s_sint[oI], ci=s_cost[oI], sj=s_sint[oJ], cj=s_cost[oJ];
        float sa=s_sina[oJ], ca=s_cosa[oJ];
        fd[3] = sj*ci - cj*si;
        fd[4] = cj*ci + sj*si;
        fd[5] = sa*ci - ca*si;
        fd[6] = ca*ci + sa*si;
        fd[7] = s_velx[oJ]-s_velx[oI];
        fd[8] = s_vely[oJ]-s_vely[oI];
        fd[9] = 1.f;
    }
    __syncthreads();

    // ---- build Gs for net g : 4 warps x 6 rows (stores tf32-rounded) ----
    {
        const int wg = tg >> 5, l = tg & 31;
        const float* w1 = sW1 + g*576;
        const float* b1 = sB1 + g*64;
        float* Gn = Gs + g*24*GPITCH;
        const int jb = (g==0)?0:((g==1)?2:5);
        const int je = (g==0)?2:((g==1)?5:8);
        #pragma unroll
        for (int rr = 0; rr < 6; rr++) {
            int r  = wg*6 + rr;
            int bl = r >> 3, i = r & 7;
            float acc0[10], acc1[10], accb[10];
            #pragma unroll
            for (int k=0;k<10;k++){ acc0[k]=0.f; acc1[k]=0.f; accb[k]=0.f; }
            for (int j = jb; j < je; j++) {
                const float* f = sFeat + (bl*64 + i*8 + j)*10;
                float fr[10];
                #pragma unroll
                for (int k=0;k<10;k++) fr[k]=f[k];
                float h0 = b1[2*l], h1 = b1[2*l+1];
                #pragma unroll
                for (int k=0;k<9;k++){
                    h0 = fmaf(fr[k], w1[k*64+2*l],   h0);
                    h1 = fmaf(fr[k], w1[k*64+2*l+1], h1);
                }
                h0 = (h0>0.f)? h0 : 0.01f*h0;
                h1 = (h1>0.f)? h1 : 0.01f*h1;
                #pragma unroll
                for (int k=0;k<10;k++){
                    acc0[k] = fmaf(h0, fr[k], acc0[k]);
                    acc1[k] = fmaf(h1, fr[k], acc1[k]);
                    accb[k] += fr[k];
                }
            }
            float* gr = Gn + r*GPITCH;
            #pragma unroll
            for (int k=0;k<10;k++){
                gr[(2*l)*10 + k]   = tf32f(acc0[k]);
                gr[(2*l+1)*10 + k] = tf32f(acc1[k]);
            }
            if (l == 0){
                #pragma unroll
                for (int k=0;k<10;k++) gr[640+k] = tf32f(accb[k]);
            }
        }
    }
    // zero pad K=650..675
    for (int idx = t; idx < 3*24*26; idx += 384) {
        int n = idx / (24*26), rem = idx - n*(24*26);
        int r = rem / 26, c = 650 + rem % 26;
        Gs[(n*24 + r)*GPITCH + c] = 0.f;
    }
    __syncthreads();

    // ---- GEMM via tf32 mma.sync, software-pipelined ----
    const int wI = t >> 5, lane = t & 31;
    const int g2 = wI >> 2;           // net 0..2
    const int nh = wI & 3;            // col group: cols nh*16..nh*16+15
    const int qid = lane >> 2, tid4 = lane & 3;

    float D[2][2][4];
    #pragma unroll
    for (int a=0;a<2;a++)
        #pragma unroll
        for (int b=0;b<2;b++)
            #pragma unroll
            for (int c=0;c<4;c++) D[a][b][c]=0.f;
    {
        const float* gr0 = Gs + (g2*24 + qid)*GPITCH;
        const float* gr1 = gr0 + 8*GPITCH;
        const float* gr2 = gr0 + 16*GPITCH;
        const float* Mn = g_Mred + g2*KPAD*64;
        const int c0 = nh*16 + qid;

        uint32_t ca0[4], ca1[4], cb[4];
        // peel: load kb=0
        {
            const int k = 0;
            ca0[0] = __float_as_uint(gr0[k+tid4]);
            ca0[1] = __float_as_uint(gr1[k+tid4]);
            ca0[2] = __float_as_uint(gr0[k+tid4+4]);
            ca0[3] = __float_as_uint(gr1[k+tid4+4]);
            ca1[0] = __float_as_uint(gr2[k+tid4]);
            ca1[1] = 0u;
            ca1[2] = __float_as_uint(gr2[k+tid4+4]);
            ca1[3] = 0u;
            cb[0] = __float_as_uint(Mn[(k+tid4)*64 + c0]);
            cb[1] = __float_as_uint(Mn[(k+tid4+4)*64 + c0]);
            cb[2] = __float_as_uint(Mn[(k+tid4)*64 + c0 + 8]);
            cb[3] = __float_as_uint(Mn[(k+tid4+4)*64 + c0 + 8]);
        }
        #pragma unroll 2
        for (int kb = 0; kb < NKB-1; kb++) {
            const int kn = (kb+1)*8;
            uint32_t na0[4], na1[4], nb[4];
            nb[0] = __float_as_uint(Mn[(kn+tid4)*64 + c0]);
            nb[1] = __float_as_uint(Mn[(kn+tid4+4)*64 + c0]);
            nb[2] = __float_as_uint(Mn[(kn+tid4)*64 + c0 + 8]);
            nb[3] = __float_as_uint(Mn[(kn+tid4+4)*64 + c0 + 8]);
            na0[0] = __float_as_uint(gr0[kn+tid4]);
            na0[1] = __float_as_uint(gr1[kn+tid4]);
            na0[2] = __float_as_uint(gr0[kn+tid4+4]);
            na0[3] = __float_as_uint(gr1[kn+tid4+4]);
            na1[0] = __float_as_uint(gr2[kn+tid4]);
            na1[1] = 0u;
            na1[2] = __float_as_uint(gr2[kn+tid4+4]);
            na1[3] = 0u;

            mma_tf32(D[0][0], ca0, cb[0], cb[1]);
            mma_tf32(D[1][0], ca1, cb[0], cb[1]);
            mma_tf32(D[0][1], ca0, cb[2], cb[3]);
            mma_tf32(D[1][1], ca1, cb[2], cb[3]);

            #pragma unroll
            for (int q=0;q<4;q++){ ca0[q]=na0[q]; ca1[q]=na1[q]; cb[q]=nb[q]; }
        }
        // tail
        mma_tf32(D[0][0], ca0, cb[0], cb[1]);
        mma_tf32(D[1][0], ca1, cb[0], cb[1]);
        mma_tf32(D[0][1], ca0, cb[2], cb[3]);
        mma_tf32(D[1][1], ca1, cb[2], cb[3]);
    }
    __syncthreads();   // all Gs reads done before reuse

    // ---- write per-net partials: sP[3][24][64] in reused Gs ----
    float* sP = Gs;
    {
        float* base = sP + g2*1536;
        #pragma unroll
        for (int nt=0; nt<2; nt++){
            int c = nh*16 + nt*8 + tid4*2;
            base[ qid     *64 + c]   = D[0][nt][0];
            base[ qid     *64 + c+1] = D[0][nt][1];
            base[(qid+8)  *64 + c]   = D[0][nt][2];
            base[(qid+8)  *64 + c+1] = D[0][nt][3];
            base[(16+qid) *64 + c]   = D[1][nt][0];
            base[(16+qid) *64 + c+1] = D[1][nt][1];
        }
    }
    __syncthreads();

    float* sX = Gs + 36864;          // [24][68]
    {
        const float4* p4 = (const float4*)sP;
        float4 x0 = p4[t], x1 = p4[384 + t], x2 = p4[768 + t];
        float4 o;
        o.x = fmaxf(x0.x + x1.x + x2.x, 0.f);
        o.y = fmaxf(x0.y + x1.y + x2.y, 0.f);
        o.z = fmaxf(x0.z + x1.z + x2.z, 0.f);
        o.w = fmaxf(x0.w + x1.w + x2.w, 0.f);
        int r = (t*4) >> 6, c = (t*4) & 63;
        *(float4*)(sX + r*68 + c) = o;
    }
    if (t < 72) {
        int r = t / 3, cc = t % 3;
        int bl = r >> 3, i = r & 7;
        float v;
        if (cc == 0) v = s_act[bl*3+0];
        else {
            float sb = s_act[bl*3+1], cb2 = s_act[bl*3+2];
            float si = s_sint[bl*8+i], ci = s_cost[bl*8+i];
            v = (cc == 1) ? (sb*ci - cb2*si) : (cb2*ci + sb*si);
        }
        sX[r*68 + 64 + cc] = fmaxf(v, 0.f);
    }
    __syncthreads();

    // ---- fc1 + fc2 : 12 warps, warp w -> rows 2w, 2w+1 ----
    const int w = t >> 5, l = t & 31;
    float fb0 = fc1b[l], fb1 = fc1b[l+32];
    float w20 = fc2w[l], w21 = fc2w[l+32];
    #pragma unroll
    for (int rr = 0; rr < 2; rr++) {
        int r = w*2 + rr;
        const float* xr = sX + r*68;
        float v0 = fb0, v1 = fb1;
        #pragma unroll
        for (int c = 0; c < 67; c++) {
            float xv = xr[c];
            v0 = fmaf(xv, sF[c*64 + l],      v0);
            v1 = fmaf(xv, sF[c*64 + l + 32], v1);
        }
        v0 = fmaxf(v0, 0.f);
        v1 = fmaxf(v1, 0.f);
        int rowg = ba0*8 + r;
        out[NBA + rowg*64 + l]      = v0;
        out[NBA + rowg*64 + l + 32] = v1;
        float qp = v0*w20 + v1*w21;
        #pragma unroll
        for (int off=16; off; off>>=1) qp += __shfl_down_sync(0xffffffffu, qp, off);
        if (l == 0) s_q[r] = qp;
    }
    __syncthreads();
    if (t < 3) {
        float s = 0.f;
        #pragma unroll
        for (int k=0;k<8;k++) s += s_q[t*8+k];
        out[ba0 + t] = s*0.125f + fc2b[0];
    }
}

// ---------------- launch ----------------
extern "C" void kernel_launch(void* const* d_in, const int* in_sizes, int n_in,
                              void* d_out, int out_size) {
    const float* inputs = (const float*)d_in[0];
    const float* actions = (const float*)d_in[2];
    const float* hA1w=(const float*)d_in[3],  *hA1b=(const float*)d_in[4];
    const float* hA2w=(const float*)d_in[5],  *hA2b=(const float*)d_in[6];
    const float* hE1w=(const float*)d_in[7],  *hE1b=(const float*)d_in[8];
    const float* hE2w=(const float*)d_in[9],  *hE2b=(const float*)d_in[10];
    const float* hL1w=(const float*)d_in[11], *hL1b=(const float*)d_in[12];
    const float* hL2w=(const float*)d_in[13], *hL2b=(const float*)d_in[14];
    const float* mergw=(const float*)d_in[15];
    const float* fc1w=(const float*)d_in[16], *fc1b=(const float*)d_in[17];
    const float* fc2w=(const float*)d_in[18], *fc2b=(const float*)d_in[19];
    float* out = (float*)d_out;

    const int smem_bytes = 57052 * 4;   // 228208 B
    cudaFuncSetAttribute(k_fused, cudaFuncAttributeMaxDynamicSharedMemorySize, smem_bytes);

    dim3 g0(KPAD, 3);
    k_mred<<<g0, 64>>>(hA2w,hA2b,hE2w,hE2b,hL2w,hL2b,mergw);
    k_fused<<<128, 384, smem_bytes>>>(inputs, actions,
                                      hA1w,hA1b,hE1w,hE1b,hL1w,hL1b,
                                      fc1w,fc1b,fc2w,fc2b, out);
}

// round 14
// speedup vs baseline: 1.0021x; 1.0021x over previous
#include <cuda_runtime.h>
#include <math.h>
#include <stdint.h>

// ---------------------------------------------------------------------------
// RDHAgent forward. R14: single kernel. Each of the 128 co-resident blocks
// computes a 1/128 slice of Mred (phase 0), signals via monotonic counter
// (graph-replay-safe), builds Gs, spin-waits for all slices (free by then),
// then runs the R12-proven tf32 mma.sync GEMM + epilogue.
// ---------------------------------------------------------------------------

#define NBA   384
#define KNET  650
#define KPAD  672
#define GPITCH 676

__device__ float g_Mred[3 * KPAD * 64];   // tf32-pre-rounded
__device__ unsigned g_ctr = 0;            // monotonic across graph replays

__device__ __forceinline__ uint32_t cvt_tf32(float x){
    uint32_t r; asm("cvt.rna.tf32.f32 %0, %1;" : "=r"(r) : "f"(x)); return r;
}
__device__ __forceinline__ float tf32f(float x){
    return __uint_as_float(cvt_tf32(x));
}
__device__ __forceinline__ void mma_tf32(float* d, const uint32_t* a, uint32_t b0, uint32_t b1){
    asm("mma.sync.aligned.m16n8k8.row.col.f32.tf32.tf32.f32 "
        "{%0,%1,%2,%3},{%4,%5,%6,%7},{%8,%9},{%0,%1,%2,%3};"
        : "+f"(d[0]),"+f"(d[1]),"+f"(d[2]),"+f"(d[3])
        : "r"(a[0]),"r"(a[1]),"r"(a[2]),"r"(a[3]), "r"(b0),"r"(b1));
}

// ---------------- K1: fused (sole kernel) ----------------
// Shared layout (floats):
//   Gs @0:48672 (reused: sP[3][24][64] @0, sX[24][68] @36864)
//   sW1 @48672:1728, sB1 @50400:192, sFeat @50592:1920,
//   sS @52512:256 scalars (incl. barrier base), sF @52768:4288 (fc1w)
//   total 57056 floats = 228224 B
__global__ void __launch_bounds__(384, 1) k_fused(
    const float* __restrict__ obs, const float* __restrict__ acts,
    const float* __restrict__ wA1, const float* __restrict__ bA1,
    const float* __restrict__ wE1, const float* __restrict__ bE1,
    const float* __restrict__ wL1, const float* __restrict__ bL1,
    const float* __restrict__ wA2, const float* __restrict__ bA2,
    const float* __restrict__ wE2, const float* __restrict__ bE2,
    const float* __restrict__ wL2, const float* __restrict__ bL2,
    const float* __restrict__ mergw,
    const float* __restrict__ fc1w, const float* __restrict__ fc1b,
    const float* __restrict__ fc2w, const float* __restrict__ fc2b,
    float* __restrict__ out)
{
    extern __shared__ float sm[];
    float* Gs    = sm;
    float* sW1   = sm + 48672;
    float* sB1   = sm + 50400;
    float* sFeat = sm + 50592;
    float* sS    = sm + 52512;
    float* sF    = sm + 52768;   // fc1w [67][64]
    float* s_velx = sS;        // [24]
    float* s_vely = sS + 24;
    float* s_sint = sS + 48;
    float* s_cost = sS + 72;
    float* s_sina = sS + 96;
    float* s_cosa = sS + 120;
    float* s_rbf  = sS + 144;  // [24][3]
    float* s_act  = sS + 216;  // [3][3]
    float* s_q    = sS + 228;  // [24]
    unsigned* s_base = (unsigned*)(sS + 252);

    const int t   = threadIdx.x;
    const int g   = t >> 7;            // build-phase net group 0..2
    const int tg  = t & 127;
    const int ba0 = blockIdx.x * 3;

    // ---- phase 0: this block's 1/128 slice of Mred (1008 elements) ----
    {
        int fbase = blockIdx.x * 1008;
        for (int i = t; i < 1008; i += 384) {
            int flat = fbase + i;
            int dh = flat & 63;
            int Kn = flat >> 6;           // net*672 + K
            int K  = Kn % KPAD;
            int net = Kn / KPAD;
            float outv = 0.f;
            if (K < KNET) {
                float m0 = mergw[dh], m1 = mergw[64+dh], m2 = mergw[128+dh], m3 = mergw[192+dh];
                float mx = fmaxf(fmaxf(m0,m1), fmaxf(m2,m3));
                float e0 = expf(m0-mx), e1 = expf(m1-mx), e2 = expf(m2-mx), e3 = expf(m3-mx);
                float inv = 1.f/(e0+e1+e2+e3);
                int j10 = K/10;
                int k   = K - j10*10;
                const float* w2 = (net==0)?wA2:((net==1)?wE2:wL2);
                const float* b2 = (net==0)?bA2:((net==1)?bE2:bL2);
                const float* src = (j10 < 64) ? (w2 + j10*2560) : b2;
                int base = k*256 + dh;
                outv = (e0*src[base] + e1*src[base+64] + e2*src[base+128] + e3*src[base+192]) * inv;
            }
            g_Mred[flat] = tf32f(outv);
        }
    }
    __syncthreads();
    if (t == 0) {
        __threadfence();
        unsigned old = atomicAdd(&g_ctr, 1u);
        *s_base = old - (old & 127u);     // launch-start value (multiple of 128)
    }

    // ---- stage fc1w early ----
    {
        const float4* f4 = (const float4*)fc1w;
        float4* d4 = (float4*)sF;
        for (int idx = t; idx < 67*16; idx += 384) d4[idx] = f4[idx];
    }

    // ---- stage W1/b1 ----
    for (int idx = t; idx < 576; idx += 384) {
        sW1[idx] = wA1[idx]; sW1[576+idx] = wE1[idx]; sW1[1152+idx] = wL1[idx];
    }
    if (t < 192) {
        int n = t >> 6, c = t & 63;
        sB1[n*64+c] = (n==0)?bA1[c]:((n==1)?bE1[c]:bL1[c]);
    }

    // ---- per-entity scalars ----
    if (t < 24) {
        int bl = t >> 3, j = t & 7;
        const float* ob = obs + (ba0 + bl)*30;
        float px,py,vx,vy;
        if (j < 2)      { px=ob[10+2*j];     py=ob[11+2*j];     vx=ob[20+2*j];     vy=ob[21+2*j]; }
        else if (j < 5) { px=ob[14+2*(j-2)]; py=ob[15+2*(j-2)]; vx=ob[24+2*(j-2)]; vy=ob[25+2*(j-2)]; }
        else            { px=ob[4+2*(j-5)];  py=ob[5+2*(j-5)];  vx=-ob[0];         vy=-ob[1]; }
        float dist = sqrtf(px*px+py*py);
        float id = 1.f/(dist+1e-7f);
        s_sint[t]=py*id; s_cost[t]=px*id;
        float vn = sqrtf(vx*vx+vy*vy);
        float iv = 1.f/(vn+1e-7f);
        s_sina[t]=vy*iv; s_cosa[t]=vx*iv;
        s_velx[t]=vx; s_vely[t]=vy;
        s_rbf[t*3+0]=expf(-0.02f*dist*dist);
        float d1=dist-5.f;  s_rbf[t*3+1]=expf(-0.02f*d1*d1);
        float d2=dist-10.f; s_rbf[t*3+2]=expf(-0.02f*d2*d2);
    } else if (t < 27) {
        int bl = t - 24;
        float ax = acts[(ba0+bl)*2], ay = acts[(ba0+bl)*2+1];
        float an = sqrtf(ax*ax+ay*ay);
        s_act[bl*3+0]=an; s_act[bl*3+1]=ay/(an+1e-7f); s_act[bl*3+2]=ax/(an+1e-7f);
    }
    __syncthreads();

    // ---- feat'[10] per (bl,i,j) ----
    if (t < 192) {
        int bl = t >> 6, i = (t >> 3) & 7, j = t & 7;
        int oI = bl*8 + i, oJ = bl*8 + j;
        float* fd = sFeat + t*10;
        fd[0] = s_rbf[oJ*3+0];
        fd[1] = s_rbf[oJ*3+1];
        fd[2] = s_rbf[oJ*3+2];
        float si=s_sint[oI], ci=s_cost[oI], sj=s_sint[oJ], cj=s_cost[oJ];
        float sa=s_sina[oJ], ca=s_cosa[oJ];
        fd[3] = sj*ci - cj*si;
        fd[4] = cj*ci + sj*si;
        fd[5] = sa*ci - ca*si;
        fd[6] = ca*ci + sa*si;
        fd[7] = s_velx[oJ]-s_velx[oI];
        fd[8] = s_vely[oJ]-s_vely[oI];
        fd[9] = 1.f;
    }
    __syncthreads();

    // ---- build Gs for net g : 4 warps x 6 rows (stores tf32-rounded) ----
    {
        const int wg = tg >> 5, l = tg & 31;
        const float* w1 = sW1 + g*576;
        const float* b1 = sB1 + g*64;
        float* Gn = Gs + g*24*GPITCH;
        const int jb = (g==0)?0:((g==1)?2:5);
        const int je = (g==0)?2:((g==1)?5:8);
        #pragma unroll
        for (int rr = 0; rr < 6; rr++) {
            int r  = wg*6 + rr;
            int bl = r >> 3, i = r & 7;
            float acc0[10], acc1[10], accb[10];
            #pragma unroll
            for (int k=0;k<10;k++){ acc0[k]=0.f; acc1[k]=0.f; accb[k]=0.f; }
            for (int j = jb; j < je; j++) {
                const float* f = sFeat + (bl*64 + i*8 + j)*10;
                float fr[10];
                #pragma unroll
                for (int k=0;k<10;k++) fr[k]=f[k];
                float h0 = b1[2*l], h1 = b1[2*l+1];
                #pragma unroll
                for (int k=0;k<9;k++){
                    h0 = fmaf(fr[k], w1[k*64+2*l],   h0);
                    h1 = fmaf(fr[k], w1[k*64+2*l+1], h1);
                }
                h0 = (h0>0.f)? h0 : 0.01f*h0;
                h1 = (h1>0.f)? h1 : 0.01f*h1;
                #pragma unroll
                for (int k=0;k<10;k++){
                    acc0[k] = fmaf(h0, fr[k], acc0[k]);
                    acc1[k] = fmaf(h1, fr[k], acc1[k]);
                    accb[k] += fr[k];
                }
            }
            float* gr = Gn + r*GPITCH;
            #pragma unroll
            for (int k=0;k<10;k++){
                gr[(2*l)*10 + k]   = tf32f(acc0[k]);
                gr[(2*l+1)*10 + k] = tf32f(acc1[k]);
            }
            if (l == 0){
                #pragma unroll
                for (int k=0;k<10;k++) gr[640+k] = tf32f(accb[k]);
            }
        }
    }
    // zero pad K=650..675
    for (int idx = t; idx < 3*24*26; idx += 384) {
        int n = idx / (24*26), rem = idx - n*(24*26);
        int r = rem / 26, c = 650 + rem % 26;
        Gs[(n*24 + r)*GPITCH + c] = 0.f;
    }
    __syncthreads();

    // ---- wait for all Mred slices (typically already done) ----
    if (t == 0) {
        unsigned base = *s_base;
        while ((*(volatile unsigned*)&g_ctr) - base < 128u) { }
        __threadfence();
    }
    __syncthreads();

    // ---- GEMM via tf32 mma.sync (R12-proven loop) ----
    const int wI = t >> 5, lane = t & 31;
    const int g2 = wI >> 2;           // net 0..2
    const int nh = wI & 3;            // col group: cols nh*16..nh*16+15
    const int qid = lane >> 2, tid4 = lane & 3;

    float D[2][2][4];
    #pragma unroll
    for (int a=0;a<2;a++)
        #pragma unroll
        for (int b=0;b<2;b++)
            #pragma unroll
            for (int c=0;c<4;c++) D[a][b][c]=0.f;
    {
        const float* gr0 = Gs + (g2*24 + qid)*GPITCH;
        const float* gr1 = gr0 + 8*GPITCH;
        const float* gr2 = gr0 + 16*GPITCH;
        const float* Mn = g_Mred + g2*KPAD*64;
        const int c0 = nh*16 + qid;

        #pragma unroll 2
        for (int k = 0; k < KPAD; k += 8) {
            uint32_t a0[4], a1[4];
            a0[0] = __float_as_uint(gr0[k+tid4]);
            a0[1] = __float_as_uint(gr1[k+tid4]);
            a0[2] = __float_as_uint(gr0[k+tid4+4]);
            a0[3] = __float_as_uint(gr1[k+tid4+4]);
            a1[0] = __float_as_uint(gr2[k+tid4]);
            a1[1] = 0u;
            a1[2] = __float_as_uint(gr2[k+tid4+4]);
            a1[3] = 0u;
            uint32_t b00 = __float_as_uint(Mn[(k+tid4)*64 + c0]);
            uint32_t b01 = __float_as_uint(Mn[(k+tid4+4)*64 + c0]);
            uint32_t b10 = __float_as_uint(Mn[(k+tid4)*64 + c0 + 8]);
            uint32_t b11 = __float_as_uint(Mn[(k+tid4+4)*64 + c0 + 8]);
            mma_tf32(D[0][0], a0, b00, b01);
            mma_tf32(D[1][0], a1, b00, b01);
            mma_tf32(D[0][1], a0, b10, b11);
            mma_tf32(D[1][1], a1, b10, b11);
        }
    }
    __syncthreads();   // all Gs reads done before reuse

    // ---- write per-net partials: sP[3][24][64] in reused Gs ----
    float* sP = Gs;
    {
        float* base = sP + g2*1536;
        #pragma unroll
        for (int nt=0; nt<2; nt++){
            int c = nh*16 + nt*8 + tid4*2;
            base[ qid     *64 + c]   = D[0][nt][0];
            base[ qid     *64 + c+1] = D[0][nt][1];
            base[(qid+8)  *64 + c]   = D[0][nt][2];
            base[(qid+8)  *64 + c+1] = D[0][nt][3];
            base[(16+qid) *64 + c]   = D[1][nt][0];
            base[(16+qid) *64 + c+1] = D[1][nt][1];
        }
    }
    __syncthreads();

    float* sX = Gs + 36864;          // [24][68]
    {
        const float4* p4 = (const float4*)sP;
        float4 x0 = p4[t], x1 = p4[384 + t], x2 = p4[768 + t];
        float4 o;
        o.x = fmaxf(x0.x + x1.x + x2.x, 0.f);
        o.y = fmaxf(x0.y + x1.y + x2.y, 0.f);
        o.z = fmaxf(x0.z + x1.z + x2.z, 0.f);
        o.w = fmaxf(x0.w + x1.w + x2.w, 0.f);
        int r = (t*4) >> 6, c = (t*4) & 63;
        *(float4*)(sX + r*68 + c) = o;
    }
    if (t < 72) {
        int r = t / 3, cc = t % 3;
        int bl = r >> 3, i = r & 7;
        float v;
        if (cc == 0) v = s_act[bl*3+0];
        else {
            float sb = s_act[bl*3+1], cb2 = s_act[bl*3+2];
            float si = s_sint[bl*8+i], ci = s_cost[bl*8+i];
            v = (cc == 1) ? (sb*ci - cb2*si) : (cb2*ci + sb*si);
        }
        sX[r*68 + 64 + cc] = fmaxf(v, 0.f);
    }
    __syncthreads();

    // ---- fc1 + fc2 : 12 warps, warp w -> rows 2w, 2w+1 ----
    const int w = t >> 5, l = t & 31;
    float fb0 = fc1b[l], fb1 = fc1b[l+32];
    float w20 = fc2w[l], w21 = fc2w[l+32];
    #pragma unroll
    for (int rr = 0; rr < 2; rr++) {
        int r = w*2 + rr;
        const float* xr = sX + r*68;
        float v0 = fb0, v1 = fb1;
        #pragma unroll
        for (int c = 0; c < 67; c++) {
            float xv = xr[c];
            v0 = fmaf(xv, sF[c*64 + l],      v0);
            v1 = fmaf(xv, sF[c*64 + l + 32], v1);
        }
        v0 = fmaxf(v0, 0.f);
        v1 = fmaxf(v1, 0.f);
        int rowg = ba0*8 + r;
        out[NBA + rowg*64 + l]      = v0;
        out[NBA + rowg*64 + l + 32] = v1;
        float qp = v0*w20 + v1*w21;
        #pragma unroll
        for (int off=16; off; off>>=1) qp += __shfl_down_sync(0xffffffffu, qp, off);
        if (l == 0) s_q[r] = qp;
    }
    __syncthreads();
    if (t < 3) {
        float s = 0.f;
        #pragma unroll
        for (int k=0;k<8;k++) s += s_q[t*8+k];
        out[ba0 + t] = s*0.125f + fc2b[0];
    }
}

// ---------------- launch ----------------
extern "C" void kernel_launch(void* const* d_in, const int* in_sizes, int n_in,
                              void* d_out, int out_size) {
    const float* inputs = (const float*)d_in[0];
    const float* actions = (const float*)d_in[2];
    const float* hA1w=(const float*)d_in[3],  *hA1b=(const float*)d_in[4];
    const float* hA2w=(const float*)d_in[5],  *hA2b=(const float*)d_in[6];
    const float* hE1w=(const float*)d_in[7],  *hE1b=(const float*)d_in[8];
    const float* hE2w=(const float*)d_in[9],  *hE2b=(const float*)d_in[10];
    const float* hL1w=(const float*)d_in[11], *hL1b=(const float*)d_in[12];
    const float* hL2w=(const float*)d_in[13], *hL2b=(const float*)d_in[14];
    const float* mergw=(const float*)d_in[15];
    const float* fc1w=(const float*)d_in[16], *fc1b=(const float*)d_in[17];
    const float* fc2w=(const float*)d_in[18], *fc2b=(const float*)d_in[19];
    float* out = (float*)d_out;

    const int smem_bytes = 57056 * 4;   // 228224 B
    cudaFuncSetAttribute(k_fused, cudaFuncAttributeMaxDynamicSharedMemorySize, smem_bytes);

    k_fused<<<128, 384, smem_bytes>>>(inputs, actions,
                                      hA1w,hA1b,hE1w,hE1b,hL1w,hL1b,
                                      hA2w,hA2b,hE2w,hE2b,hL2w,hL2b, mergw,
                                      fc1w,fc1b,fc2w,fc2b, out);
}

// round 15
// speedup vs baseline: 1.1306x; 1.1282x over previous
#include <cuda_runtime.h>
#include <math.h>
#include <stdint.h>

// ---------------------------------------------------------------------------
// RDHAgent forward. R15: R12 base (two kernels, tf32 mma.sync, compiler-
// scheduled loop) with B in fragment-coalesced order: per (net,kb,nh,nt),
// lane reads one float2 {b_row=tid4, b_row=tid4+4} -> 2 coalesced LDG.64
// per kb per warp (was 4 scattered scalar LDGs = ~16 wavefronts).
// ---------------------------------------------------------------------------

#define NBA   384
#define KNET  650
#define KPAD  672
#define NKB   (KPAD/8)      // 84
#define GPITCH 676

__device__ float g_Mfrag[3 * NKB * 4 * 2 * 32 * 2];   // 516 KB, tf32-rounded

__device__ __forceinline__ uint32_t cvt_tf32(float x){
    uint32_t r; asm("cvt.rna.tf32.f32 %0, %1;" : "=r"(r) : "f"(x)); return r;
}
__device__ __forceinline__ float tf32f(float x){
    return __uint_as_float(cvt_tf32(x));
}
__device__ __forceinline__ void mma_tf32(float* d, const uint32_t* a, uint32_t b0, uint32_t b1){
    asm("mma.sync.aligned.m16n8k8.row.col.f32.tf32.tf32.f32 "
        "{%0,%1,%2,%3},{%4,%5,%6,%7},{%8,%9},{%0,%1,%2,%3};"
        : "+f"(d[0]),"+f"(d[1]),"+f"(d[2]),"+f"(d[3])
        : "r"(a[0]),"r"(a[1]),"r"(a[2]),"r"(a[3]), "r"(b0),"r"(b1));
}

// ---------------- K0: build fragment-ordered tf32 B ----------------
// Element (net, K, dh): K = kb*8 + kin, kin = slot*4 + tid4 (slot: +0/+4 row);
// dh = col = nh*16 + nt*8 + qid; fragment lane = qid*4 + tid4.
__global__ void k_mred(const float* __restrict__ wA2, const float* __restrict__ bA2,
                       const float* __restrict__ wE2, const float* __restrict__ bE2,
                       const float* __restrict__ wL2, const float* __restrict__ bL2,
                       const float* __restrict__ mergw) {
    int K = blockIdx.x, net = blockIdx.y, dh = threadIdx.x;
    float outv = 0.f;
    if (K < KNET) {
        float m0 = mergw[dh], m1 = mergw[64+dh], m2 = mergw[128+dh], m3 = mergw[192+dh];
        float mx = fmaxf(fmaxf(m0,m1), fmaxf(m2,m3));
        float e0 = expf(m0-mx), e1 = expf(m1-mx), e2 = expf(m2-mx), e3 = expf(m3-mx);
        float inv = 1.f/(e0+e1+e2+e3);
        int j10 = K/10;
        int k   = K - j10*10;
        const float* w2 = (net==0)?wA2:((net==1)?wE2:wL2);
        const float* b2 = (net==0)?bA2:((net==1)?bE2:bL2);
        const float* src = (j10 < 64) ? (w2 + j10*2560) : b2;
        int base = k*256 + dh;
        outv = (e0*src[base] + e1*src[base+64] + e2*src[base+128] + e3*src[base+192]) * inv;
    }
    int kb = K >> 3, kin = K & 7;
    int slot = kin >> 2, tid4 = kin & 3;
    int qid = dh & 7, nt = (dh >> 3) & 1, nh = dh >> 4;
    int lane = qid*4 + tid4;
    g_Mfrag[((((net*NKB + kb)*4 + nh)*2 + nt)*32 + lane)*2 + slot] = tf32f(outv);
}

// ---------------- K1: fused ----------------
// Shared layout (floats): Gs @0:48672 (reused sP @0, sX @36864),
// sW1 @48672:1728, sB1 @50400:192, sFeat @50592:1920, sS @52512:252,
// sF @52764:4288. total 57052 floats = 228208 B.
__global__ void __launch_bounds__(384, 1) k_fused(
    const float* __restrict__ obs, const float* __restrict__ acts,
    const float* __restrict__ wA1, const float* __restrict__ bA1,
    const float* __restrict__ wE1, const float* __restrict__ bE1,
    const float* __restrict__ wL1, const float* __restrict__ bL1,
    const float* __restrict__ fc1w, const float* __restrict__ fc1b,
    const float* __restrict__ fc2w, const float* __restrict__ fc2b,
    float* __restrict__ out)
{
    extern __shared__ float sm[];
    float* Gs    = sm;
    float* sW1   = sm + 48672;
    float* sB1   = sm + 50400;
    float* sFeat = sm + 50592;
    float* sS    = sm + 52512;
    float* sF    = sm + 52764;   // fc1w [67][64]
    float* s_velx = sS;        // [24]
    float* s_vely = sS + 24;
    float* s_sint = sS + 48;
    float* s_cost = sS + 72;
    float* s_sina = sS + 96;
    float* s_cosa = sS + 120;
    float* s_rbf  = sS + 144;  // [24][3]
    float* s_act  = sS + 216;  // [3][3]
    float* s_q    = sS + 228;  // [24]

    const int t   = threadIdx.x;
    const int g   = t >> 7;            // build-phase net group 0..2
    const int tg  = t & 127;
    const int ba0 = blockIdx.x * 3;

    // ---- stage fc1w early ----
    {
        const float4* f4 = (const float4*)fc1w;
        float4* d4 = (float4*)sF;
        for (int idx = t; idx < 67*16; idx += 384) d4[idx] = f4[idx];
    }

    // ---- stage W1/b1 ----
    for (int idx = t; idx < 576; idx += 384) {
        sW1[idx] = wA1[idx]; sW1[576+idx] = wE1[idx]; sW1[1152+idx] = wL1[idx];
    }
    if (t < 192) {
        int n = t >> 6, c = t & 63;
        sB1[n*64+c] = (n==0)?bA1[c]:((n==1)?bE1[c]:bL1[c]);
    }

    // ---- per-entity scalars ----
    if (t < 24) {
        int bl = t >> 3, j = t & 7;
        const float* ob = obs + (ba0 + bl)*30;
        float px,py,vx,vy;
        if (j < 2)      { px=ob[10+2*j];     py=ob[11+2*j];     vx=ob[20+2*j];     vy=ob[21+2*j]; }
        else if (j < 5) { px=ob[14+2*(j-2)]; py=ob[15+2*(j-2)]; vx=ob[24+2*(j-2)]; vy=ob[25+2*(j-2)]; }
        else            { px=ob[4+2*(j-5)];  py=ob[5+2*(j-5)];  vx=-ob[0];         vy=-ob[1]; }
        float dist = sqrtf(px*px+py*py);
        float id = 1.f/(dist+1e-7f);
        s_sint[t]=py*id; s_cost[t]=px*id;
        float vn = sqrtf(vx*vx+vy*vy);
        float iv = 1.f/(vn+1e-7f);
        s_sina[t]=vy*iv; s_cosa[t]=vx*iv;
        s_velx[t]=vx; s_vely[t]=vy;
        s_rbf[t*3+0]=expf(-0.02f*dist*dist);
        float d1=dist-5.f;  s_rbf[t*3+1]=expf(-0.02f*d1*d1);
        float d2=dist-10.f; s_rbf[t*3+2]=expf(-0.02f*d2*d2);
    } else if (t < 27) {
        int bl = t - 24;
        float ax = acts[(ba0+bl)*2], ay = acts[(ba0+bl)*2+1];
        float an = sqrtf(ax*ax+ay*ay);
        s_act[bl*3+0]=an; s_act[bl*3+1]=ay/(an+1e-7f); s_act[bl*3+2]=ax/(an+1e-7f);
    }
    __syncthreads();

    // ---- feat'[10] per (bl,i,j) ----
    if (t < 192) {
        int bl = t >> 6, i = (t >> 3) & 7, j = t & 7;
        int oI = bl*8 + i, oJ = bl*8 + j;
        float* fd = sFeat + t*10;
        fd[0] = s_rbf[oJ*3+0];
        fd[1] = s_rbf[oJ*3+1];
        fd[2] = s_rbf[oJ*3+2];
        float si=s_sint[oI], ci=s_cost[oI], sj=s_sint[oJ], cj=s_cost[oJ];
        float sa=s_sina[oJ], ca=s_cosa[oJ];
        fd[3] = sj*ci - cj*si;
        fd[4] = cj*ci + sj*si;
        fd[5] = sa*ci - ca*si;
        fd[6] = ca*ci + sa*si;
        fd[7] = s_velx[oJ]-s_velx[oI];
        fd[8] = s_vely[oJ]-s_vely[oI];
        fd[9] = 1.f;
    }
    __syncthreads();

    // ---- build Gs for net g : 4 warps x 6 rows (stores tf32-rounded) ----
    {
        const int wg = tg >> 5, l = tg & 31;
        const float* w1 = sW1 + g*576;
        const float* b1 = sB1 + g*64;
        float* Gn = Gs + g*24*GPITCH;
        const int jb = (g==0)?0:((g==1)?2:5);
        const int je = (g==0)?2:((g==1)?5:8);
        #pragma unroll
        for (int rr = 0; rr < 6; rr++) {
            int r  = wg*6 + rr;
            int bl = r >> 3, i = r & 7;
            float acc0[10], acc1[10], accb[10];
            #pragma unroll
            for (int k=0;k<10;k++){ acc0[k]=0.f; acc1[k]=0.f; accb[k]=0.f; }
            for (int j = jb; j < je; j++) {
                const float* f = sFeat + (bl*64 + i*8 + j)*10;
                float fr[10];
                #pragma unroll
                for (int k=0;k<10;k++) fr[k]=f[k];
                float h0 = b1[2*l], h1 = b1[2*l+1];
                #pragma unroll
                for (int k=0;k<9;k++){
                    h0 = fmaf(fr[k], w1[k*64+2*l],   h0);
                    h1 = fmaf(fr[k], w1[k*64+2*l+1], h1);
                }
                h0 = (h0>0.f)? h0 : 0.01f*h0;
                h1 = (h1>0.f)? h1 : 0.01f*h1;
                #pragma unroll
                for (int k=0;k<10;k++){
                    acc0[k] = fmaf(h0, fr[k], acc0[k]);
                    acc1[k] = fmaf(h1, fr[k], acc1[k]);
                    accb[k] += fr[k];
                }
            }
            float* gr = Gn + r*GPITCH;
            #pragma unroll
            for (int k=0;k<10;k++){
                gr[(2*l)*10 + k]   = tf32f(acc0[k]);
                gr[(2*l+1)*10 + k] = tf32f(acc1[k]);
            }
            if (l == 0){
                #pragma unroll
                for (int k=0;k<10;k++) gr[640+k] = tf32f(accb[k]);
            }
        }
    }
    // zero pad K=650..675
    for (int idx = t; idx < 3*24*26; idx += 384) {
        int n = idx / (24*26), rem = idx - n*(24*26);
        int r = rem / 26, c = 650 + rem % 26;
        Gs[(n*24 + r)*GPITCH + c] = 0.f;
    }
    __syncthreads();

    // ---- GEMM via tf32 mma.sync (R12 loop, fragment-coalesced B) ----
    const int wI = t >> 5, lane = t & 31;
    const int g2 = wI >> 2;           // net 0..2
    const int nh = wI & 3;            // col group: cols nh*16..nh*16+15
    const int qid = lane >> 2, tid4 = lane & 3;

    float D[2][2][4];
    #pragma unroll
    for (int a=0;a<2;a++)
        #pragma unroll
        for (int b=0;b<2;b++)
            #pragma unroll
            for (int c=0;c<4;c++) D[a][b][c]=0.f;
    {
        const float* gr0 = Gs + (g2*24 + qid)*GPITCH;
        const float* gr1 = gr0 + 8*GPITCH;
        const float* gr2 = gr0 + 16*GPITCH;
        // float2 index: (net*NKB+kb)*256 + nh*64 + nt*32 + lane
        const float2* Bp = (const float2*)g_Mfrag + g2*NKB*256 + nh*64 + lane;

        #pragma unroll 2
        for (int kb = 0; kb < NKB; kb++) {
            const int k = kb*8;
            uint32_t a0[4], a1[4];
            a0[0] = __float_as_uint(gr0[k+tid4]);
            a0[1] = __float_as_uint(gr1[k+tid4]);
            a0[2] = __float_as_uint(gr0[k+tid4+4]);
            a0[3] = __float_as_uint(gr1[k+tid4+4]);
            a1[0] = __float_as_uint(gr2[k+tid4]);
            a1[1] = 0u;
            a1[2] = __float_as_uint(gr2[k+tid4+4]);
            a1[3] = 0u;
            float2 f0 = Bp[kb*256];
            float2 f1 = Bp[kb*256 + 32];
            uint32_t b00 = __float_as_uint(f0.x), b01 = __float_as_uint(f0.y);
            uint32_t b10 = __float_as_uint(f1.x), b11 = __float_as_uint(f1.y);
            mma_tf32(D[0][0], a0, b00, b01);
            mma_tf32(D[1][0], a1, b00, b01);
            mma_tf32(D[0][1], a0, b10, b11);
            mma_tf32(D[1][1], a1, b10, b11);
        }
    }
    __syncthreads();   // all Gs reads done before reuse

    // ---- write per-net partials: sP[3][24][64] in reused Gs ----
    float* sP = Gs;
    {
        float* base = sP + g2*1536;
        #pragma unroll
        for (int nt=0; nt<2; nt++){
            int c = nh*16 + nt*8 + tid4*2;
            base[ qid     *64 + c]   = D[0][nt][0];
            base[ qid     *64 + c+1] = D[0][nt][1];
            base[(qid+8)  *64 + c]   = D[0][nt][2];
            base[(qid+8)  *64 + c+1] = D[0][nt][3];
            base[(16+qid) *64 + c]   = D[1][nt][0];
            base[(16+qid) *64 + c+1] = D[1][nt][1];
        }
    }
    __syncthreads();

    float* sX = Gs + 36864;          // [24][68]
    {
        const float4* p4 = (const float4*)sP;
        float4 x0 = p4[t], x1 = p4[384 + t], x2 = p4[768 + t];
        float4 o;
        o.x = fmaxf(x0.x + x1.x + x2.x, 0.f);
        o.y = fmaxf(x0.y + x1.y + x2.y, 0.f);
        o.z = fmaxf(x0.z + x1.z + x2.z, 0.f);
        o.w = fmaxf(x0.w + x1.w + x2.w, 0.f);
        int r = (t*4) >> 6, c = (t*4) & 63;
        *(float4*)(sX + r*68 + c) = o;
    }
    if (t < 72) {
        int r = t / 3, cc = t % 3;
        int bl = r >> 3, i = r & 7;
        float v;
        if (cc == 0) v = s_act[bl*3+0];
        else {
            float sb = s_act[bl*3+1], cb2 = s_act[bl*3+2];
            float si = s_sint[bl*8+i], ci = s_cost[bl*8+i];
            v = (cc == 1) ? (sb*ci - cb2*si) : (cb2*ci + sb*si);
        }
        sX[r*68 + 64 + cc] = fmaxf(v, 0.f);
    }
    __syncthreads();

    // ---- fc1 + fc2 : 12 warps, warp w -> rows 2w, 2w+1 ----
    const int w = t >> 5, l = t & 31;
    float fb0 = fc1b[l], fb1 = fc1b[l+32];
    float w20 = fc2w[l], w21 = fc2w[l+32];
    #pragma unroll
    for (int rr = 0; rr < 2; rr++) {
        int r = w*2 + rr;
        const float* xr = sX + r*68;
        float v0 = fb0, v1 = fb1;
        #pragma unroll
        for (int c = 0; c < 67; c++) {
            float xv = xr[c];
            v0 = fmaf(xv, sF[c*64 + l],      v0);
            v1 = fmaf(xv, sF[c*64 + l + 32], v1);
        }
        v0 = fmaxf(v0, 0.f);
        v1 = fmaxf(v1, 0.f);
        int rowg = ba0*8 + r;
        out[NBA + rowg*64 + l]      = v0;
        out[NBA + rowg*64 + l + 32] = v1;
        float qp = v0*w20 + v1*w21;
        #pragma unroll
        for (int off=16; off; off>>=1) qp += __shfl_down_sync(0xffffffffu, qp, off);
        if (l == 0) s_q[r] = qp;
    }
    __syncthreads();
    if (t < 3) {
        float s = 0.f;
        #pragma unroll
        for (int k=0;k<8;k++) s += s_q[t*8+k];
        out[ba0 + t] = s*0.125f + fc2b[0];
    }
}

// ---------------- launch ----------------
extern "C" void kernel_launch(void* const* d_in, const int* in_sizes, int n_in,
                              void* d_out, int out_size) {
    const float* inputs = (const float*)d_in[0];
    const float* actions = (const float*)d_in[2];
    const float* hA1w=(const float*)d_in[3],  *hA1b=(const float*)d_in[4];
    const float* hA2w=(const float*)d_in[5],  *hA2b=(const float*)d_in[6];
    const float* hE1w=(const float*)d_in[7],  *hE1b=(const float*)d_in[8];
    const float* hE2w=(const float*)d_in[9],  *hE2b=(const float*)d_in[10];
    const float* hL1w=(const float*)d_in[11], *hL1b=(const float*)d_in[12];
    const float* hL2w=(const float*)d_in[13], *hL2b=(const float*)d_in[14];
    const float* mergw=(const float*)d_in[15];
    const float* fc1w=(const float*)d_in[16], *fc1b=(const float*)d_in[17];
    const float* fc2w=(const float*)d_in[18], *fc2b=(const float*)d_in[19];
    float* out = (float*)d_out;

    const int smem_bytes = 57052 * 4;   // 228208 B
    cudaFuncSetAttribute(k_fused, cudaFuncAttributeMaxDynamicSharedMemorySize, smem_bytes);

    dim3 g0(KPAD, 3);
    k_mred<<<g0, 64>>>(hA2w,hA2b,hE2w,hE2b,hL2w,hL2b,mergw);
    k_fused<<<128, 384, smem_bytes>>>(inputs, actions,
                                      hA1w,hA1b,hE1w,hE1b,hL1w,hL1b,
                                      fc1w,fc1b,fc2w,fc2b, out);
}